// round 12
// baseline (speedup 1.0000x reference)
#include <cuda_runtime.h>
#include <cuda_bf16.h>
#include <cstdint>

// Problem constants
#define NTOK   4096
#define DMODEL 1024
#define DHID   16384
#define TOPK   64

#define T_F      1.0f        // candidate threshold (validity self-checked per row)
#define NSEG     (DHID/128)  // 32 candidate segments per row (one per n-tile CTA)
#define SEGCAP   64          // slots per (row, segment)
#define CROW     (NSEG*SEGCAP)  // 2048 candidate slots per row
#define BAND_EPS 0.024f      // ~10 sigma of bf16-GEMM noise
#define BAND_CAP 192

// -------- device scratch (no allocations allowed) --------
__device__ float              g_z [(size_t)NTOK * DHID];   // dense z~ (also fallback source)
__device__ int                g_si[NTOK * TOPK];
__device__ float              g_sv[NTOK * TOPK];
__device__ __nv_bfloat16      g_xh[(size_t)NTOK * DMODEL]; // bf16(x)
__device__ __nv_bfloat16      g_wh[(size_t)DHID * DMODEL]; // bf16(W_enc^T) [n][k]
__device__ float              g_wt[(size_t)DHID * DMODEL]; // fp32 W_enc^T  [n][k]
__device__ int                g_scnt[NTOK * NSEG];         // per-(row,seg) counts (plain stores)
__device__ int                g_fb[NTOK];                  // fallback flags (topk writes always)
__device__ unsigned long long g_cand[(size_t)NTOK * CROW]; // (col<<32)|f32bits

// ============================================================
// PTX helpers (plain compute_103 legal)
// ============================================================
__device__ __forceinline__ uint32_t smem_u32(const void* p) {
    uint32_t a;
    asm("{ .reg .u64 t; cvta.to.shared.u64 t, %1; cvt.u32.u64 %0, t; }"
        : "=r"(a) : "l"(p));
    return a;
}
__device__ __forceinline__ void cp16(uint32_t saddr, const void* gaddr) {
    asm volatile("cp.async.ca.shared.global [%0], [%1], 16;" :: "r"(saddr), "l"(gaddr));
}
#define CP_COMMIT() asm volatile("cp.async.commit_group;" ::: "memory")
#define CP_WAIT1()  asm volatile("cp.async.wait_group 1;" ::: "memory")

#define LDSM_X4(r0, r1, r2, r3, addr) \
    asm volatile("ldmatrix.sync.aligned.m8n8.x4.shared.b16 {%0,%1,%2,%3}, [%4];" \
                 : "=r"(r0), "=r"(r1), "=r"(r2), "=r"(r3) : "r"(addr))

__device__ __forceinline__ void mma16816(float* c,
                                         uint32_t a0, uint32_t a1, uint32_t a2, uint32_t a3,
                                         uint32_t b0, uint32_t b1)
{
    asm volatile(
        "mma.sync.aligned.m16n8k16.row.col.f32.bf16.bf16.f32 "
        "{%0,%1,%2,%3}, {%4,%5,%6,%7}, {%8,%9}, {%0,%1,%2,%3};"
        : "+f"(c[0]), "+f"(c[1]), "+f"(c[2]), "+f"(c[3])
        : "r"(a0), "r"(a1), "r"(a2), "r"(a3), "r"(b0), "r"(b1));
}

// ============================================================
// Conversions
// ============================================================
__global__ void convert_x_kernel(const float* __restrict__ x)
{
    int i = blockIdx.x * 256 + threadIdx.x;
    g_xh[i] = __float2bfloat16(x[i]);
}

// W_enc [k=1024][n=16384]  ->  g_wt/g_wh [n][k] (transposed)
__global__ __launch_bounds__(256)
void convert_w_kernel(const float* __restrict__ W)
{
    __shared__ float t[32][33];
    const int n0 = blockIdx.x * 32;
    const int k0 = blockIdx.y * 32;
    const int tx = threadIdx.x & 31;
    const int ty = threadIdx.x >> 5;
#pragma unroll
    for (int r = ty; r < 32; r += 8)
        t[r][tx] = W[(size_t)(k0 + r) * DHID + n0 + tx];
    __syncthreads();
#pragma unroll
    for (int r = ty; r < 32; r += 8) {
        float v = t[tx][r];                   // = W[k0+tx][n0+r]
        size_t o = (size_t)(n0 + r) * DMODEL + k0 + tx;
        g_wt[o] = v;
        g_wh[o] = __float2bfloat16(v);
    }
}

// ============================================================
// Encode (approx) via mma.sync. Dense g_z store + segmented
// candidate push: smem counters (ATOMS), plain global stores —
// NO global atomics anywhere.
// ============================================================
#define ROWB   144
#define TILEB  (128 * ROWB)
#define STAGEB (2 * TILEB)
#define ENC_SMEM (2 * STAGEB)                   // 73728 B

__global__ __launch_bounds__(256, 2)
void encode_mma_kernel(const float* __restrict__ bias)
{
    extern __shared__ __align__(16) char dsm[];
    const uint32_t sbase = smem_u32(dsm);
    const int tid  = threadIdx.x;
    const int lane = tid & 31;
    const int wid  = tid >> 5;
    const int wm   = wid >> 2;
    const int wn   = wid & 3;
    const int m0   = blockIdx.x * 128;
    const int n0   = blockIdx.y * 128;
    const int seg  = blockIdx.y;                // candidate segment id

    const __nv_bfloat16* gA = g_xh + (size_t)m0 * DMODEL;
    const __nv_bfloat16* gB = g_wh + (size_t)n0 * DMODEL;

    float accr[4][4][4];
#pragma unroll
    for (int i = 0; i < 4; ++i)
#pragma unroll
        for (int j = 0; j < 4; ++j)
#pragma unroll
            for (int q = 0; q < 4; ++q) accr[i][j][q] = 0.0f;

    auto load_stage = [&](int st, int c) {
        const int k0 = c * 64;
        const uint32_t sA = sbase + st * STAGEB;
        const uint32_t sB = sA + TILEB;
#pragma unroll
        for (int i = 0; i < 4; ++i) {
            int id = tid + 256 * i;
            int r  = id >> 3;
            int cc = id & 7;
            cp16(sA + r * ROWB + cc * 16, gA + (size_t)r * DMODEL + k0 + cc * 8);
            cp16(sB + r * ROWB + cc * 16, gB + (size_t)r * DMODEL + k0 + cc * 8);
        }
    };

    load_stage(0, 0);
    CP_COMMIT();

    for (int c = 0; c < DMODEL / 64; ++c) {
        if (c + 1 < DMODEL / 64) load_stage((c + 1) & 1, c + 1);
        CP_COMMIT();
        CP_WAIT1();
        __syncthreads();

        const uint32_t sA = sbase + (c & 1) * STAGEB;
        const uint32_t sB = sA + TILEB;
        const uint32_t aRow = (uint32_t)(wm * 64 + (lane & 15));
        const uint32_t aCol = (uint32_t)((lane >> 4) << 4);
        const uint32_t bRow = (uint32_t)(wn * 32 + (lane & 7) + ((lane >> 4) << 3));
        const uint32_t bCol = (uint32_t)(((lane >> 3) & 1) << 4);

#pragma unroll
        for (int kt = 0; kt < 4; ++kt) {
            uint32_t a[4][4];
#pragma unroll
            for (int mt = 0; mt < 4; ++mt)
                LDSM_X4(a[mt][0], a[mt][1], a[mt][2], a[mt][3],
                        sA + (aRow + mt * 16) * ROWB + kt * 32 + aCol);
            uint32_t b[2][4];
#pragma unroll
            for (int np = 0; np < 2; ++np)
                LDSM_X4(b[np][0], b[np][1], b[np][2], b[np][3],
                        sB + (bRow + np * 16) * ROWB + kt * 32 + bCol);
#pragma unroll
            for (int mt = 0; mt < 4; ++mt)
#pragma unroll
                for (int nt = 0; nt < 4; ++nt)
                    mma16816(accr[mt][nt],
                             a[mt][0], a[mt][1], a[mt][2], a[mt][3],
                             b[nt >> 1][(nt & 1) * 2], b[nt >> 1][(nt & 1) * 2 + 1]);
        }
        __syncthreads();
    }

    // ---- epilogue: dense z store + segmented candidate push ----
    int* scnt = (int*)dsm;                      // reuse smem (mainloop done)
    if (tid < 128) scnt[tid] = 0;
    __syncthreads();

#pragma unroll
    for (int nt = 0; nt < 4; ++nt) {
        const int col = n0 + wn * 32 + nt * 8 + 2 * (lane & 3);
        const float bv0 = bias[col];
        const float bv1 = bias[col + 1];
#pragma unroll
        for (int mt = 0; mt < 4; ++mt) {
            const int lr = wm * 64 + mt * 16 + (lane >> 2);   // local row 0..127
            float v[4];
            v[0] = fmaxf(accr[mt][nt][0] + bv0, 0.0f);
            v[1] = fmaxf(accr[mt][nt][1] + bv1, 0.0f);
            v[2] = fmaxf(accr[mt][nt][2] + bv0, 0.0f);
            v[3] = fmaxf(accr[mt][nt][3] + bv1, 0.0f);
            *(float2*)&g_z[(size_t)(m0 + lr) * DHID + col]     = make_float2(v[0], v[1]);
            *(float2*)&g_z[(size_t)(m0 + lr + 8) * DHID + col] = make_float2(v[2], v[3]);
#pragma unroll
            for (int q = 0; q < 4; ++q) {
                if (v[q] > T_F) {
                    const int r = lr + (q >> 1) * 8;
                    const int cc = col + (q & 1);
                    int p = atomicAdd(&scnt[r], 1);           // smem atomic only
                    if (p < SEGCAP)
                        g_cand[(size_t)(m0 + r) * CROW + seg * SEGCAP + p] =
                            ((unsigned long long)(unsigned)cc << 32) | __float_as_uint(v[q]);
                }
            }
        }
    }
    __syncthreads();
    if (tid < 128)                              // plain store; written EVERY launch
        g_scnt[(m0 + tid) * NSEG + seg] = scnt[tid];
}

// ============================================================
// Top-64 from segmented candidate lists. Self-validating; flags
// g_fb (written on EVERY path -> no zero kernel needed). Band
// resolved by fp64 rescore -> selected SET == true top-64.
// Values emitted are z~ (sigma ~2.3e-3 -> ~2e-5 global rel err).
// ============================================================
__global__ __launch_bounds__(256)
void topk_kernel(const float* __restrict__ x)
{
    __shared__ float    s_cv[CROW];
    __shared__ int      s_ci[CROW];
    __shared__ int      s_off[NSEG + 1];
    __shared__ int      s_c[NSEG];
    __shared__ unsigned hist[256];
    __shared__ unsigned s_prefix, s_need, s_nout, s_nb;
    __shared__ int      s_bad;
    __shared__ int      s_bi[BAND_CAP];
    __shared__ float    s_bv[BAND_CAP];
    __shared__ double   s_bs[BAND_CAP];
    __shared__ double   s_red[8];
    __shared__ int      s_oi[TOPK];
    __shared__ float    s_ov[TOPK];

    const int row = blockIdx.x;
    const int tid = threadIdx.x;

    if (tid < NSEG) s_c[tid] = g_scnt[row * NSEG + tid];
    if (tid == 0) s_bad = 0;
    __syncthreads();
    if (tid == 0) {
        int acc = 0;
        for (int s = 0; s < NSEG; ++s) {
            int c = s_c[s];
            if (c > SEGCAP) s_bad = 1;          // segment overflow
            s_off[s] = acc;
            acc += c;
        }
        s_off[NSEG] = acc;
        if (acc < TOPK) s_bad = 1;              // not enough candidates
        s_prefix = 0u; s_need = TOPK; s_nout = 0u; s_nb = 0u;
    }
    __syncthreads();

    if (!s_bad) {
        // gather segments into compact smem list
        for (int s = 0; s < NSEG; ++s) {
            const int c = s_c[s];
            for (int i = tid; i < c; i += 256) {
                unsigned long long e = g_cand[(size_t)row * CROW + s * SEGCAP + i];
                s_ci[s_off[s] + i] = (int)(e >> 32);
                s_cv[s_off[s] + i] = __uint_as_float((unsigned)(e & 0xffffffffu));
            }
        }
        const int cnt = s_off[NSEG];
        __syncthreads();

        // 4-round radix select -> 64th-largest z~ key
        for (int rr = 0; rr < 4; ++rr) {
            hist[tid] = 0u;
            __syncthreads();
            unsigned pfx = s_prefix;
            int shift = 24 - 8 * rr;
            for (int i = tid; i < cnt; i += 256) {
                unsigned key = __float_as_uint(s_cv[i]);
                bool ok = (rr == 0) || ((key >> (shift + 8)) == pfx);
                if (ok) atomicAdd(&hist[(key >> shift) & 255u], 1u);
            }
            __syncthreads();
            if (tid == 0) {
                unsigned need = s_need, cum = 0;
                int b;
                for (b = 255; b >= 0; --b) {
                    unsigned c = hist[b];
                    if (cum + c >= need) break;
                    cum += c;
                }
                if (b < 0) b = 0;
                s_need   = need - cum;
                s_prefix = (pfx << 8) | (unsigned)b;
            }
            __syncthreads();
        }

        const float v64 = __uint_as_float(s_prefix);
        if (tid == 0 && !(v64 - BAND_EPS > T_F)) s_bad = 1;   // band may cross T_F
        __syncthreads();

        if (!s_bad) {
            const float bhi = v64 + BAND_EPS;
            const float blo = v64 - BAND_EPS;
            for (int i = tid; i < cnt; i += 256) {
                float z = s_cv[i];
                if (z > bhi) {
                    unsigned p = atomicAdd(&s_nout, 1u);
                    s_oi[p] = s_ci[i];
                    s_ov[p] = z;
                } else if (z >= blo) {
                    unsigned q = atomicAdd(&s_nb, 1u);
                    if (q < BAND_CAP) { s_bi[q] = s_ci[i]; s_bv[q] = z; }
                }
            }
            __syncthreads();
            if (tid == 0 && s_nb > BAND_CAP) s_bad = 1;
            __syncthreads();

            if (!s_bad) {
                const int nb    = (int)s_nb;
                const int base  = (int)s_nout;
                const int slots = TOPK - base;

                if (nb == slots) {
                    if (tid < nb) { s_oi[base + tid] = s_bi[tid]; s_ov[base + tid] = s_bv[tid]; }
                } else {
                    for (int b = 0; b < nb; ++b) {           // fp64 rescore (true values)
                        const int f = s_bi[b];
                        const float* wr = g_wt + (size_t)f * DMODEL;
                        double part = 0.0;
                        for (int k = tid; k < DMODEL; k += 256)
                            part += (double)x[(size_t)row * DMODEL + k] * (double)wr[k];
#pragma unroll
                        for (int o = 16; o > 0; o >>= 1)
                            part += __shfl_down_sync(0xffffffffu, part, o);
                        if ((tid & 31) == 0) s_red[tid >> 5] = part;
                        __syncthreads();
                        if (tid == 0) {
                            double s = 0.0;
#pragma unroll
                            for (int w = 0; w < 8; ++w) s += s_red[w];
                            s_bs[b] = s;
                        }
                        __syncthreads();
                    }
                    if (tid < nb) {
                        double mv = s_bs[tid];
                        int    mi = s_bi[tid];
                        int rank = 0;
                        for (int j = 0; j < nb; ++j)
                            if (s_bs[j] > mv || (s_bs[j] == mv && s_bi[j] < mi)) ++rank;
                        if (rank < slots) {
                            unsigned p = atomicAdd(&s_nout, 1u);
                            s_oi[p] = mi;
                            s_ov[p] = s_bv[tid];
                        }
                    }
                }
                __syncthreads();

                if (tid < TOPK) {                           // index-sorted deterministic out
                    int my = s_oi[tid];
                    unsigned rank = 0;
#pragma unroll
                    for (int j = 0; j < TOPK; ++j) rank += (s_oi[j] < my) ? 1u : 0u;
                    g_si[row * TOPK + rank] = my;
                    g_sv[row * TOPK + rank] = s_ov[tid];
                }
            }
        }
    }
    __syncthreads();
    if (tid == 0) g_fb[row] = s_bad;            // written on EVERY path
}

// ============================================================
// Fallback for flagged rows: cheap now — scans the precomputed
// dense g_z row (no GEMM recompute). Same radix+band+fp64 logic.
// ============================================================
__global__ __launch_bounds__(256)
void fallback_kernel(const float* __restrict__ x)
{
    __shared__ unsigned hist[256];
    __shared__ unsigned s_prefix, s_need, s_nout, s_nb;
    __shared__ int      s_bi[BAND_CAP];
    __shared__ float    s_bv[BAND_CAP];
    __shared__ double   s_bs[BAND_CAP];
    __shared__ double   s_red[8];
    __shared__ int      s_oi[TOPK];
    __shared__ float    s_ov[TOPK];

    const int row = blockIdx.x;
    const int tid = threadIdx.x;
    if (!g_fb[row]) return;

    const float* __restrict__ zr = g_z + (size_t)row * DHID;
    if (tid == 0) { s_prefix = 0u; s_need = TOPK; }
    __syncthreads();

    for (int rr = 0; rr < 4; ++rr) {
        hist[tid] = 0u;
        __syncthreads();
        unsigned pfx = s_prefix;
        int shift = 24 - 8 * rr;
        for (int i = tid; i < DHID; i += 256) {
            unsigned key = __float_as_uint(zr[i]);
            bool ok = (rr == 0) || ((key >> (shift + 8)) == pfx);
            if (ok) atomicAdd(&hist[(key >> shift) & 255u], 1u);
        }
        __syncthreads();
        if (tid == 0) {
            unsigned need = s_need, cum = 0;
            int b;
            for (b = 255; b >= 0; --b) {
                unsigned c = hist[b];
                if (cum + c >= need) break;
                cum += c;
            }
            if (b < 0) b = 0;
            s_need   = need - cum;
            s_prefix = (pfx << 8) | (unsigned)b;
        }
        __syncthreads();
    }

    const float v64 = __uint_as_float(s_prefix);
    const float bhi = v64 + BAND_EPS;
    const float blo = v64 - BAND_EPS;
    if (tid == 0) { s_nout = 0u; s_nb = 0u; }
    __syncthreads();

    for (int i = tid; i < DHID; i += 256) {
        float z = zr[i];
        if (z > bhi) {
            unsigned p = atomicAdd(&s_nout, 1u);
            s_oi[p] = i;
            s_ov[p] = z;
        } else if (z >= blo) {
            unsigned q = atomicAdd(&s_nb, 1u);
            if (q < BAND_CAP) { s_bi[q] = i; s_bv[q] = z; }
        }
    }
    __syncthreads();

    const int nb    = (int)min(s_nb, (unsigned)BAND_CAP);
    const int base  = (int)s_nout;
    const int slots = TOPK - base;

    if (nb == slots) {
        if (tid < nb) { s_oi[base + tid] = s_bi[tid]; s_ov[base + tid] = s_bv[tid]; }
    } else {
        for (int b = 0; b < nb; ++b) {
            const int f = s_bi[b];
            const float* wr = g_wt + (size_t)f * DMODEL;
            double part = 0.0;
            for (int k = tid; k < DMODEL; k += 256)
                part += (double)x[(size_t)row * DMODEL + k] * (double)wr[k];
#pragma unroll
            for (int o = 16; o > 0; o >>= 1)
                part += __shfl_down_sync(0xffffffffu, part, o);
            if ((tid & 31) == 0) s_red[tid >> 5] = part;
            __syncthreads();
            if (tid == 0) {
                double s = 0.0;
#pragma unroll
                for (int w = 0; w < 8; ++w) s += s_red[w];
                s_bs[b] = s;
            }
            __syncthreads();
        }
        if (tid < nb) {
            double mv = s_bs[tid];
            int    mi = s_bi[tid];
            int rank = 0;
            for (int j = 0; j < nb; ++j)
                if (s_bs[j] > mv || (s_bs[j] == mv && s_bi[j] < mi)) ++rank;
            if (rank < slots) {
                unsigned p = atomicAdd(&s_nout, 1u);
                s_oi[p] = mi;
                s_ov[p] = s_bv[tid];
            }
        }
    }
    __syncthreads();

    if (tid < TOPK) {
        int my = s_oi[tid];
        unsigned rank = 0;
#pragma unroll
        for (int j = 0; j < TOPK; ++j) rank += (s_oi[j] < my) ? 1u : 0u;
        g_si[row * TOPK + rank] = my;
        g_sv[row * TOPK + rank] = s_ov[tid];
    }
}

// ============================================================
// Decode: y[row] = b_dec + sum_f sel_val * W_dec[sel_idx, :]
// ============================================================
__global__ __launch_bounds__(256)
void decode_kernel(const float* __restrict__ Wd,
                   const float* __restrict__ bd,
                   float* __restrict__ y)
{
    __shared__ int   si[TOPK];
    __shared__ float sv[TOPK];
    const int row = blockIdx.x;
    const int tid = threadIdx.x;

    if (tid < TOPK) {
        si[tid] = g_si[row * TOPK + tid];
        sv[tid] = g_sv[row * TOPK + tid];
    }
    __syncthreads();

    float4 acc = *(const float4*)&bd[4 * tid];
#pragma unroll 8
    for (int f = 0; f < TOPK; ++f) {
        float v = sv[f];
        const float4 w = *(const float4*)&Wd[(size_t)si[f] * DMODEL + 4 * tid];
        acc.x = fmaf(v, w.x, acc.x);
        acc.y = fmaf(v, w.y, acc.y);
        acc.z = fmaf(v, w.z, acc.z);
        acc.w = fmaf(v, w.w, acc.w);
    }
    *(float4*)&y[(size_t)row * DMODEL + 4 * tid] = acc;
}

// ============================================================
extern "C" void kernel_launch(void* const* d_in, const int* in_sizes, int n_in,
                              void* d_out, int out_size)
{
    const float* x     = (const float*)d_in[0];   // [4096,1024]
    const float* W_enc = (const float*)d_in[1];   // [1024,16384]
    const float* b_enc = (const float*)d_in[2];   // [16384]
    const float* W_dec = (const float*)d_in[3];   // [16384,1024]
    const float* b_dec = (const float*)d_in[4];   // [1024]
    float* y = (float*)d_out;                     // [4096,1024]

    cudaFuncSetAttribute(encode_mma_kernel,
                         cudaFuncAttributeMaxDynamicSharedMemorySize, ENC_SMEM);

    convert_x_kernel<<<NTOK * DMODEL / 256, 256>>>(x);
    convert_w_kernel<<<dim3(DHID / 32, DMODEL / 32), 256>>>(W_enc);
    encode_mma_kernel<<<dim3(NTOK / 128, DHID / 128), 256, ENC_SMEM>>>(b_enc);
    topk_kernel<<<NTOK, 256>>>(x);
    fallback_kernel<<<NTOK, 256>>>(x);
    decode_kernel<<<NTOK, 256>>>(W_dec, b_dec, y);
}

// round 14
// speedup vs baseline: 1.4927x; 1.4927x over previous
#include <cuda_runtime.h>
#include <cuda_bf16.h>
#include <cstdint>

// Problem constants
#define NTOK   4096
#define DMODEL 1024
#define DHID   16384
#define TOPK   64

#define T_F      1.0f        // candidate threshold (validity self-checked per row)
#define CCAP     2048        // per-row candidate capacity
#define BAND_EPS 0.024f      // ~10 sigma of bf16-GEMM noise
#define BAND_CAP 192

// -------- device scratch (no allocations allowed) --------
__device__ float              g_z [(size_t)NTOK * DHID];   // dense z~ (scan + fallback source)
__device__ int                g_si[NTOK * TOPK];
__device__ float              g_sv[NTOK * TOPK];
__device__ __nv_bfloat16      g_xh[(size_t)NTOK * DMODEL]; // bf16(x)
__device__ __nv_bfloat16      g_wh[(size_t)DHID * DMODEL]; // bf16(W_enc^T) [n][k]
__device__ float              g_wt[(size_t)DHID * DMODEL]; // fp32 W_enc^T  [n][k]
__device__ int                g_ccnt[NTOK];                // per-row candidate counts (plain store)
__device__ int                g_fb[NTOK];                  // fallback flags (topk writes always)
__device__ unsigned long long g_cand[(size_t)NTOK * CCAP]; // (col<<32)|f32bits

// ============================================================
// PTX helpers (plain compute_103 legal)
// ============================================================
__device__ __forceinline__ uint32_t smem_u32(const void* p) {
    uint32_t a;
    asm("{ .reg .u64 t; cvta.to.shared.u64 t, %1; cvt.u32.u64 %0, t; }"
        : "=r"(a) : "l"(p));
    return a;
}
__device__ __forceinline__ void cp16(uint32_t saddr, const void* gaddr) {
    asm volatile("cp.async.ca.shared.global [%0], [%1], 16;" :: "r"(saddr), "l"(gaddr));
}
#define CP_COMMIT() asm volatile("cp.async.commit_group;" ::: "memory")
#define CP_WAIT1()  asm volatile("cp.async.wait_group 1;" ::: "memory")

#define LDSM_X4(r0, r1, r2, r3, addr) \
    asm volatile("ldmatrix.sync.aligned.m8n8.x4.shared.b16 {%0,%1,%2,%3}, [%4];" \
                 : "=r"(r0), "=r"(r1), "=r"(r2), "=r"(r3) : "r"(addr))

__device__ __forceinline__ void mma16816(float* c,
                                         uint32_t a0, uint32_t a1, uint32_t a2, uint32_t a3,
                                         uint32_t b0, uint32_t b1)
{
    asm volatile(
        "mma.sync.aligned.m16n8k16.row.col.f32.bf16.bf16.f32 "
        "{%0,%1,%2,%3}, {%4,%5,%6,%7}, {%8,%9}, {%0,%1,%2,%3};"
        : "+f"(c[0]), "+f"(c[1]), "+f"(c[2]), "+f"(c[3])
        : "r"(a0), "r"(a1), "r"(a2), "r"(a3), "r"(b0), "r"(b1));
}

// ============================================================
// Conversions
// ============================================================
__global__ void convert_x_kernel(const float* __restrict__ x)
{
    int i = blockIdx.x * 256 + threadIdx.x;
    g_xh[i] = __float2bfloat16(x[i]);
}

// W_enc [k=1024][n=16384]  ->  g_wt/g_wh [n][k] (transposed)
__global__ __launch_bounds__(256)
void convert_w_kernel(const float* __restrict__ W)
{
    __shared__ float t[32][33];
    const int n0 = blockIdx.x * 32;
    const int k0 = blockIdx.y * 32;
    const int tx = threadIdx.x & 31;
    const int ty = threadIdx.x >> 5;
#pragma unroll
    for (int r = ty; r < 32; r += 8)
        t[r][tx] = W[(size_t)(k0 + r) * DHID + n0 + tx];
    __syncthreads();
#pragma unroll
    for (int r = ty; r < 32; r += 8) {
        float v = t[tx][r];                   // = W[k0+tx][n0+r]
        size_t o = (size_t)(n0 + r) * DMODEL + k0 + tx;
        g_wt[o] = v;
        g_wh[o] = __float2bfloat16(v);
    }
}

// ============================================================
// Encode (approx): g_z = relu(bf16(x) @ bf16(W) + b) via mma.sync.
// EXACT R10 kernel (dense store only; no candidate logic -> no
// epilogue register pressure beyond the measured 128-reg budget).
// ============================================================
#define ROWB   144
#define TILEB  (128 * ROWB)
#define STAGEB (2 * TILEB)
#define ENC_SMEM (2 * STAGEB)                   // 73728 B

__global__ __launch_bounds__(256, 2)
void encode_mma_kernel(const float* __restrict__ bias)
{
    extern __shared__ __align__(16) char dsm[];
    const uint32_t sbase = smem_u32(dsm);
    const int tid  = threadIdx.x;
    const int lane = tid & 31;
    const int wid  = tid >> 5;
    const int wm   = wid >> 2;
    const int wn   = wid & 3;
    const int m0   = blockIdx.x * 128;
    const int n0   = blockIdx.y * 128;

    const __nv_bfloat16* gA = g_xh + (size_t)m0 * DMODEL;
    const __nv_bfloat16* gB = g_wh + (size_t)n0 * DMODEL;

    float accr[4][4][4];
#pragma unroll
    for (int i = 0; i < 4; ++i)
#pragma unroll
        for (int j = 0; j < 4; ++j)
#pragma unroll
            for (int q = 0; q < 4; ++q) accr[i][j][q] = 0.0f;

    auto load_stage = [&](int st, int c) {
        const int k0 = c * 64;
        const uint32_t sA = sbase + st * STAGEB;
        const uint32_t sB = sA + TILEB;
#pragma unroll
        for (int i = 0; i < 4; ++i) {
            int id = tid + 256 * i;
            int r  = id >> 3;
            int cc = id & 7;
            cp16(sA + r * ROWB + cc * 16, gA + (size_t)r * DMODEL + k0 + cc * 8);
            cp16(sB + r * ROWB + cc * 16, gB + (size_t)r * DMODEL + k0 + cc * 8);
        }
    };

    load_stage(0, 0);
    CP_COMMIT();

    for (int c = 0; c < DMODEL / 64; ++c) {
        if (c + 1 < DMODEL / 64) load_stage((c + 1) & 1, c + 1);
        CP_COMMIT();
        CP_WAIT1();
        __syncthreads();

        const uint32_t sA = sbase + (c & 1) * STAGEB;
        const uint32_t sB = sA + TILEB;
        const uint32_t aRow = (uint32_t)(wm * 64 + (lane & 15));
        const uint32_t aCol = (uint32_t)((lane >> 4) << 4);
        const uint32_t bRow = (uint32_t)(wn * 32 + (lane & 7) + ((lane >> 4) << 3));
        const uint32_t bCol = (uint32_t)(((lane >> 3) & 1) << 4);

#pragma unroll
        for (int kt = 0; kt < 4; ++kt) {
            uint32_t a[4][4];
#pragma unroll
            for (int mt = 0; mt < 4; ++mt)
                LDSM_X4(a[mt][0], a[mt][1], a[mt][2], a[mt][3],
                        sA + (aRow + mt * 16) * ROWB + kt * 32 + aCol);
            uint32_t b[2][4];
#pragma unroll
            for (int np = 0; np < 2; ++np)
                LDSM_X4(b[np][0], b[np][1], b[np][2], b[np][3],
                        sB + (bRow + np * 16) * ROWB + kt * 32 + bCol);
#pragma unroll
            for (int mt = 0; mt < 4; ++mt)
#pragma unroll
                for (int nt = 0; nt < 4; ++nt)
                    mma16816(accr[mt][nt],
                             a[mt][0], a[mt][1], a[mt][2], a[mt][3],
                             b[nt >> 1][(nt & 1) * 2], b[nt >> 1][(nt & 1) * 2 + 1]);
        }
        __syncthreads();
    }

    // ---- epilogue: bias + relu, dense stores only (R10 verbatim) ----
#pragma unroll
    for (int nt = 0; nt < 4; ++nt) {
        const int col = n0 + wn * 32 + nt * 8 + 2 * (lane & 3);
        const float bv0 = bias[col];
        const float bv1 = bias[col + 1];
#pragma unroll
        for (int mt = 0; mt < 4; ++mt) {
            const int row = m0 + wm * 64 + mt * 16 + (lane >> 2);
            float2 o0, o1;
            o0.x = fmaxf(accr[mt][nt][0] + bv0, 0.0f);
            o0.y = fmaxf(accr[mt][nt][1] + bv1, 0.0f);
            o1.x = fmaxf(accr[mt][nt][2] + bv0, 0.0f);
            o1.y = fmaxf(accr[mt][nt][3] + bv1, 0.0f);
            *(float2*)&g_z[(size_t)row * DHID + col]       = o0;
            *(float2*)&g_z[(size_t)(row + 8) * DHID + col] = o1;
        }
    }
}

// ============================================================
// Scan: one block per row, single coalesced float4 pass over g_z,
// push z~ > T_F candidates to the per-row list (smem counter only;
// count written by plain store every launch).
// ============================================================
__global__ __launch_bounds__(256)
void scan_kernel()
{
    __shared__ int s_cnt;
    const int row = blockIdx.x;
    const int tid = threadIdx.x;
    if (tid == 0) s_cnt = 0;
    __syncthreads();

    const float4* zr = (const float4*)(g_z + (size_t)row * DHID);
    unsigned long long* out = g_cand + (size_t)row * CCAP;

#pragma unroll 4
    for (int i = tid; i < DHID / 4; i += 256) {
        float4 v = zr[i];
        const int c0 = 4 * i;
#pragma unroll
        for (int q = 0; q < 4; ++q) {
            float z = (q == 0) ? v.x : (q == 1) ? v.y : (q == 2) ? v.z : v.w;
            if (z > T_F) {
                int p = atomicAdd(&s_cnt, 1);
                if (p < CCAP)
                    out[p] = ((unsigned long long)(unsigned)(c0 + q) << 32) |
                             __float_as_uint(z);
            }
        }
    }
    __syncthreads();
    if (tid == 0) g_ccnt[row] = s_cnt;
}

// ============================================================
// Top-64 from candidate list. Self-validating (flags g_fb on every
// path). Band resolved by fp64 rescore -> selected SET == true
// top-64. Writes indices only (values recomputed exactly after).
// ============================================================
__global__ __launch_bounds__(256)
void topk_kernel(const float* __restrict__ x)
{
    __shared__ float    s_cv[CCAP];
    __shared__ int      s_ci[CCAP];
    __shared__ unsigned hist[256];
    __shared__ unsigned s_prefix, s_need, s_nout, s_nb;
    __shared__ int      s_bad;
    __shared__ int      s_bi[BAND_CAP];
    __shared__ double   s_bs[BAND_CAP];
    __shared__ double   s_red[8];
    __shared__ int      s_oi[TOPK];

    const int row = blockIdx.x;
    const int tid = threadIdx.x;
    const int cnt = g_ccnt[row];

    if (tid == 0) {
        s_bad = (cnt < TOPK || cnt > CCAP) ? 1 : 0;
        s_prefix = 0u; s_need = TOPK; s_nout = 0u; s_nb = 0u;
    }
    __syncthreads();

    if (!s_bad) {
        for (int i = tid; i < cnt; i += 256) {
            unsigned long long e = g_cand[(size_t)row * CCAP + i];
            s_ci[i] = (int)(e >> 32);
            s_cv[i] = __uint_as_float((unsigned)(e & 0xffffffffu));
        }
        __syncthreads();

        // 4-round radix select -> 64th-largest z~ key
        for (int rr = 0; rr < 4; ++rr) {
            hist[tid] = 0u;
            __syncthreads();
            unsigned pfx = s_prefix;
            int shift = 24 - 8 * rr;
            for (int i = tid; i < cnt; i += 256) {
                unsigned key = __float_as_uint(s_cv[i]);
                bool ok = (rr == 0) || ((key >> (shift + 8)) == pfx);
                if (ok) atomicAdd(&hist[(key >> shift) & 255u], 1u);
            }
            __syncthreads();
            if (tid == 0) {
                unsigned need = s_need, cum = 0;
                int b;
                for (b = 255; b >= 0; --b) {
                    unsigned c = hist[b];
                    if (cum + c >= need) break;
                    cum += c;
                }
                if (b < 0) b = 0;
                s_need   = need - cum;
                s_prefix = (pfx << 8) | (unsigned)b;
            }
            __syncthreads();
        }

        const float v64 = __uint_as_float(s_prefix);
        if (tid == 0 && !(v64 - BAND_EPS > T_F)) s_bad = 1;   // band may cross T_F
        __syncthreads();

        if (!s_bad) {
            const float bhi = v64 + BAND_EPS;
            const float blo = v64 - BAND_EPS;
            for (int i = tid; i < cnt; i += 256) {
                float z = s_cv[i];
                if (z > bhi) {
                    unsigned p = atomicAdd(&s_nout, 1u);
                    s_oi[p] = s_ci[i];
                } else if (z >= blo) {
                    unsigned q = atomicAdd(&s_nb, 1u);
                    if (q < BAND_CAP) s_bi[q] = s_ci[i];
                }
            }
            __syncthreads();
            if (tid == 0 && s_nb > BAND_CAP) s_bad = 1;
            __syncthreads();

            if (!s_bad) {
                const int nb    = (int)s_nb;
                const int base  = (int)s_nout;
                const int slots = TOPK - base;

                if (nb == slots) {
                    if (tid < nb) s_oi[base + tid] = s_bi[tid];
                } else {
                    for (int b = 0; b < nb; ++b) {            // fp64 rescore (true values)
                        const int f = s_bi[b];
                        const float* wr = g_wt + (size_t)f * DMODEL;
                        double part = 0.0;
                        for (int k = tid; k < DMODEL; k += 256)
                            part += (double)x[(size_t)row * DMODEL + k] * (double)wr[k];
#pragma unroll
                        for (int o = 16; o > 0; o >>= 1)
                            part += __shfl_down_sync(0xffffffffu, part, o);
                        if ((tid & 31) == 0) s_red[tid >> 5] = part;
                        __syncthreads();
                        if (tid == 0) {
                            double s = 0.0;
#pragma unroll
                            for (int w = 0; w < 8; ++w) s += s_red[w];
                            s_bs[b] = s;
                        }
                        __syncthreads();
                    }
                    if (tid < nb) {
                        double mv = s_bs[tid];
                        int    mi = s_bi[tid];
                        int rank = 0;
                        for (int j = 0; j < nb; ++j)
                            if (s_bs[j] > mv || (s_bs[j] == mv && s_bi[j] < mi)) ++rank;
                        if (rank < slots) {
                            unsigned p = atomicAdd(&s_nout, 1u);
                            s_oi[p] = mi;
                        }
                    }
                }
                __syncthreads();

                if (tid < TOPK) {                             // index-sorted deterministic
                    int my = s_oi[tid];
                    unsigned rank = 0;
#pragma unroll
                    for (int j = 0; j < TOPK; ++j) rank += (s_oi[j] < my) ? 1u : 0u;
                    g_si[row * TOPK + rank] = my;
                }
            }
        }
    }
    __syncthreads();
    if (tid == 0) g_fb[row] = s_bad;              // written on EVERY path
}

// ============================================================
// Fallback for flagged rows (expected 0): dense radix+band over
// the precomputed g_z row. Writes indices only.
// ============================================================
__global__ __launch_bounds__(256)
void fallback_kernel(const float* __restrict__ x)
{
    __shared__ unsigned hist[256];
    __shared__ unsigned s_prefix, s_need, s_nout, s_nb;
    __shared__ int      s_bi[BAND_CAP];
    __shared__ double   s_bs[BAND_CAP];
    __shared__ double   s_red[8];
    __shared__ int      s_oi[TOPK];

    const int row = blockIdx.x;
    const int tid = threadIdx.x;
    if (!g_fb[row]) return;

    const float* __restrict__ zr = g_z + (size_t)row * DHID;
    if (tid == 0) { s_prefix = 0u; s_need = TOPK; s_nout = 0u; s_nb = 0u; }
    __syncthreads();

    for (int rr = 0; rr < 4; ++rr) {
        hist[tid] = 0u;
        __syncthreads();
        unsigned pfx = s_prefix;
        int shift = 24 - 8 * rr;
        for (int i = tid; i < DHID; i += 256) {
            unsigned key = __float_as_uint(zr[i]);
            bool ok = (rr == 0) || ((key >> (shift + 8)) == pfx);
            if (ok) atomicAdd(&hist[(key >> shift) & 255u], 1u);
        }
        __syncthreads();
        if (tid == 0) {
            unsigned need = s_need, cum = 0;
            int b;
            for (b = 255; b >= 0; --b) {
                unsigned c = hist[b];
                if (cum + c >= need) break;
                cum += c;
            }
            if (b < 0) b = 0;
            s_need   = need - cum;
            s_prefix = (pfx << 8) | (unsigned)b;
        }
        __syncthreads();
    }

    const float v64 = __uint_as_float(s_prefix);
    const float bhi = v64 + BAND_EPS;
    const float blo = v64 - BAND_EPS;
    __syncthreads();

    for (int i = tid; i < DHID; i += 256) {
        float z = zr[i];
        if (z > bhi) {
            unsigned p = atomicAdd(&s_nout, 1u);
            s_oi[p] = i;
        } else if (z >= blo) {
            unsigned q = atomicAdd(&s_nb, 1u);
            if (q < BAND_CAP) s_bi[q] = i;
        }
    }
    __syncthreads();

    const int nb    = (int)min(s_nb, (unsigned)BAND_CAP);
    const int base  = (int)s_nout;
    const int slots = TOPK - base;

    if (nb == slots) {
        if (tid < nb) s_oi[base + tid] = s_bi[tid];
    } else {
        for (int b = 0; b < nb; ++b) {
            const int f = s_bi[b];
            const float* wr = g_wt + (size_t)f * DMODEL;
            double part = 0.0;
            for (int k = tid; k < DMODEL; k += 256)
                part += (double)x[(size_t)row * DMODEL + k] * (double)wr[k];
#pragma unroll
            for (int o = 16; o > 0; o >>= 1)
                part += __shfl_down_sync(0xffffffffu, part, o);
            if ((tid & 31) == 0) s_red[tid >> 5] = part;
            __syncthreads();
            if (tid == 0) {
                double s = 0.0;
#pragma unroll
                for (int w = 0; w < 8; ++w) s += s_red[w];
                s_bs[b] = s;
            }
            __syncthreads();
        }
        if (tid < nb) {
            double mv = s_bs[tid];
            int    mi = s_bi[tid];
            int rank = 0;
            for (int j = 0; j < nb; ++j)
                if (s_bs[j] > mv || (s_bs[j] == mv && s_bi[j] < mi)) ++rank;
            if (rank < slots) {
                unsigned p = atomicAdd(&s_nout, 1u);
                s_oi[p] = mi;
            }
        }
    }
    __syncthreads();

    if (tid < TOPK) {
        int my = s_oi[tid];
        unsigned rank = 0;
#pragma unroll
        for (int j = 0; j < TOPK; ++j) rank += (s_oi[j] < my) ? 1u : 0u;
        g_si[row * TOPK + rank] = my;
    }
}

// ============================================================
// Exact fp32 recompute of the 64 selected z values per row
// (this is what holds rel_err at ~3e-7; R12 proved skipping it
// costs 7.5e-4).
// ============================================================
__global__ __launch_bounds__(256)
void exact_kernel(const float* __restrict__ x, const float* __restrict__ be)
{
    __shared__ float sx[DMODEL];
    const int row  = blockIdx.x;
    const int tid  = threadIdx.x;
    const int w    = tid >> 5;
    const int lane = tid & 31;

    for (int i = tid; i < DMODEL; i += 256)
        sx[i] = x[(size_t)row * DMODEL + i];
    __syncthreads();
    const float4* sx4 = (const float4*)sx;

    for (int j = w; j < TOPK; j += 8) {
        const int f = g_si[row * TOPK + j];
        const float4* wr = (const float4*)(g_wt + (size_t)f * DMODEL);
        float s = 0.0f;
#pragma unroll
        for (int k4 = lane; k4 < DMODEL / 4; k4 += 32) {
            float4 xv = sx4[k4];
            float4 wv = wr[k4];
            s += xv.x * wv.x + xv.y * wv.y + xv.z * wv.z + xv.w * wv.w;
        }
#pragma unroll
        for (int o = 16; o > 0; o >>= 1)
            s += __shfl_down_sync(0xffffffffu, s, o);
        if (lane == 0)
            g_sv[row * TOPK + j] = fmaxf(s + be[f], 0.0f);
    }
}

// ============================================================
// Decode: y[row] = b_dec + sum_f sel_val * W_dec[sel_idx, :]
// ============================================================
__global__ __launch_bounds__(256)
void decode_kernel(const float* __restrict__ Wd,
                   const float* __restrict__ bd,
                   float* __restrict__ y)
{
    __shared__ int   si[TOPK];
    __shared__ float sv[TOPK];
    const int row = blockIdx.x;
    const int tid = threadIdx.x;

    if (tid < TOPK) {
        si[tid] = g_si[row * TOPK + tid];
        sv[tid] = g_sv[row * TOPK + tid];
    }
    __syncthreads();

    float4 acc = *(const float4*)&bd[4 * tid];
#pragma unroll 8
    for (int f = 0; f < TOPK; ++f) {
        float v = sv[f];
        const float4 w = *(const float4*)&Wd[(size_t)si[f] * DMODEL + 4 * tid];
        acc.x = fmaf(v, w.x, acc.x);
        acc.y = fmaf(v, w.y, acc.y);
        acc.z = fmaf(v, w.z, acc.z);
        acc.w = fmaf(v, w.w, acc.w);
    }
    *(float4*)&y[(size_t)row * DMODEL + 4 * tid] = acc;
}

// ============================================================
extern "C" void kernel_launch(void* const* d_in, const int* in_sizes, int n_in,
                              void* d_out, int out_size)
{
    const float* x     = (const float*)d_in[0];   // [4096,1024]
    const float* W_enc = (const float*)d_in[1];   // [1024,16384]
    const float* b_enc = (const float*)d_in[2];   // [16384]
    const float* W_dec = (const float*)d_in[3];   // [16384,1024]
    const float* b_dec = (const float*)d_in[4];   // [1024]
    float* y = (float*)d_out;                     // [4096,1024]

    cudaFuncSetAttribute(encode_mma_kernel,
                         cudaFuncAttributeMaxDynamicSharedMemorySize, ENC_SMEM);

    convert_x_kernel<<<NTOK * DMODEL / 256, 256>>>(x);
    convert_w_kernel<<<dim3(DHID / 32, DMODEL / 32), 256>>>(W_enc);
    encode_mma_kernel<<<dim3(NTOK / 128, DHID / 128), 256, ENC_SMEM>>>(b_enc);
    scan_kernel<<<NTOK, 256>>>();
    topk_kernel<<<NTOK, 256>>>(x);
    fallback_kernel<<<NTOK, 256>>>(x);
    exact_kernel<<<NTOK, 256>>>(x, b_enc);
    decode_kernel<<<NTOK, 256>>>(W_dec, b_dec, y);
}